// round 11
// baseline (speedup 1.0000x reference)
#include <cuda_runtime.h>
#include <cuda_fp16.h>
#include <cstdint>

// ---------------- problem constants ----------------
#define NB  16
#define HN  8
#define HDM 32
#define DM  256
#define GP  512
#define GD  128
#define NHS 128          // NB*HN slices
#define SEG 16
// (1/sqrt(32)) * log2(e)
#define EXPSC 0.2550526808750678f

// swizzled smem index: conflict-free for sink strip pattern
#define SIDX(c) ((((c) & 31) * 17) + ((c) >> 5))

// mega-kernel shared memory layout (bytes)
#define ESTR   520                       // halfs per E row (1040B: +4 banks/row)
#define SM_E   0                         // 128*520*2 = 133120
#define SM_QK  133120                    // Qs 32*137*4 =17536 ; Ks +17536 (strips alias)
#define SM_MR  168192                    // float[128]
#define SM_MC  168704                    // float[512]
#define SM_TOT 170752

// ---------------- scratch (static device globals; no runtime alloc) ------------
__device__ float  g_pg[NB*GP*DM];
__device__ float  g_dg[NB*GD*DM];
__device__ float  g_mp[NB*GP];
__device__ float  g_md[NB*GD];
__device__ float  g_part[2*NB*SEG*DM];
__device__ float  g_cpart[2*NB*SEG];
__device__ float  g_kp[NHS*GP*HDM];
__device__ float  g_qd[NHS*GD*HDM];
__device__ __half g_E [NHS*GD*GP];
__device__ float  g_r [NHS*GD];
__device__ float  g_c [NHS*GP];
__device__ int    g_maskmode;

// ---------------- tf32 + mma + ex2 helpers ---------------------------------------
__device__ __forceinline__ uint32_t tf32cvt(float x) {
    uint32_t r;
    asm("cvt.rna.tf32.f32 %0, %1;" : "=r"(r) : "f"(x));
    return r;
}
__device__ __forceinline__ void mma_tf32(float& c0, float& c1, float& c2, float& c3,
                                         uint32_t a0, uint32_t a1, uint32_t a2, uint32_t a3,
                                         uint32_t b0, uint32_t b1) {
    asm volatile(
        "mma.sync.aligned.m16n8k8.row.col.f32.tf32.tf32.f32 "
        "{%0,%1,%2,%3}, {%4,%5,%6,%7}, {%8,%9}, {%0,%1,%2,%3};"
        : "+f"(c0), "+f"(c1), "+f"(c2), "+f"(c3)
        : "r"(a0), "r"(a1), "r"(a2), "r"(a3), "r"(b0), "r"(b1));
}
__device__ __forceinline__ uint32_t ex2_f16x2(uint32_t x) {
    uint32_t r;
    asm("ex2.approx.f16x2 %0, %1;" : "=r"(r) : "r"(x));
    return r;
}

// ---------------- mask dtype probe ------------------------------------------------
__global__ void k_probe(const unsigned int* __restrict__ m) {
    __shared__ int cnt[4];
    int t = threadIdx.x;
    if (t < 4) cnt[t] = 0;
    __syncthreads();
    unsigned w = m[t];
    if (w == 0x3F803F80u || w == 0x3C003C00u) atomicAdd(&cnt[0], 1);
    if (w == 0x3F800000u)                     atomicAdd(&cnt[1], 1);
    if (w > 1u)                               atomicAdd(&cnt[2], 1);
    __syncthreads();
    if (t == 0) {
        int mode;
        if (cnt[0] >= 4)      mode = 3;
        else if (cnt[1] >= 4) mode = 0;
        else if (cnt[2] > 0)  mode = 2;
        else                  mode = 1;
        g_maskmode = mode;
    }
}

__device__ __forceinline__ float mask_at(const void* M, int tok, int mode) {
    switch (mode) {
        case 0:  return ((const float*)M)[tok] != 0.0f ? 1.0f : 0.0f;
        case 1:  return ((const int*)M)[tok]   != 0    ? 1.0f : 0.0f;
        case 2:  return ((const unsigned char*)M)[tok] ? 1.0f : 0.0f;
        default: return ((const unsigned short*)M)[tok] ? 1.0f : 0.0f;
    }
}

// ---------------- grouping --------------------------------------------------------
__global__ void k_group2(const float* __restrict__ P, const float* __restrict__ Dr,
                         const void* __restrict__ MP, const void* __restrict__ MD) {
    int b = blockIdx.x;
    const float* X; const void* M; float* out; float* mout;
    if (b < NB*GP) { X = P;  M = MP; out = g_pg; mout = g_mp; }
    else           { b -= NB*GP; X = Dr; M = MD; out = g_dg; mout = g_md; }
    int d = threadIdx.x;
    const float* src = X + (size_t)b * 4 * DM;
    out[(size_t)b * DM + d] =
        0.25f * (src[d] + src[DM + d] + src[2*DM + d] + src[3*DM + d]);
    if (d == 0) {
        int mode = g_maskmode;
        float m = mask_at(M, 4*b+0, mode) + mask_at(M, 4*b+1, mode)
                + mask_at(M, 4*b+2, mode) + mask_at(M, 4*b+3, mode);
        mout[b] = (m > 0.0f) ? 1.0f : 0.0f;
    }
}

// ---------------- fused launch 1: masked-sum partials + pipelined proj GEMM -------
#define ASTR 137
__global__ __launch_bounds__(256) void k_fuse1(const float* __restrict__ Wkp,
                                               const float* __restrict__ Wqd) {
    if (blockIdx.x < 512) {
        int s = blockIdx.x;
        int n = s & 15, ent = (s >> 4) & 1, seg = s >> 5;
        int d = threadIdx.x;
        const float* X = ent ? g_dg : g_pg;
        const float* m = ent ? g_md : g_mp;
        int G = ent ? GD : GP;
        int chunk = G / SEG;
        int g0 = seg * chunk;
        float a0 = 0.f, a1 = 0.f, a2 = 0.f, a3 = 0.f;
        for (int g = g0; g < g0 + chunk; g += 4) {
            a0 += m[n*G+g+0] * X[((size_t)(n*G+g+0))*DM + d];
            a1 += m[n*G+g+1] * X[((size_t)(n*G+g+1))*DM + d];
            a2 += m[n*G+g+2] * X[((size_t)(n*G+g+2))*DM + d];
            a3 += m[n*G+g+3] * X[((size_t)(n*G+g+3))*DM + d];
        }
        g_part[((ent*NB + n)*SEG + seg)*DM + d] = (a0 + a1) + (a2 + a3);
        if (d == 0) {
            float c = 0.0f;
            for (int g = g0; g < g0 + chunk; g++) c += m[n*G + g];
            g_cpart[(ent*NB + n)*SEG + seg] = c;
        }
        return;
    }
    // ---- projection GEMM: single TF32, CTA 128x128, K-step 32, reg-staged pipe ---
    int pb = blockIdx.x - 512;
    int bx = pb & 63, by = (pb >> 6) & 1, bz = pb >> 7;
    const float* X; const float* W; float* OUT; int L;
    if (bz == 0) { X = g_pg; W = Wkp; OUT = g_kp; L = GP; }
    else         { if (bx >= 16) return;
                   X = g_dg; W = Wqd; OUT = g_qd; L = GD; }
    __shared__ uint32_t AsH[32*ASTR];
    __shared__ uint32_t BsH[32*ASTR];

    int tid = threadIdx.x;
    int lane = tid & 31, w = tid >> 5;
    int g = lane >> 2, tk = lane & 3;
    int wm = (w & 3) * 32, wn = (w >> 2) * 64;
    int m0 = bx * 128, o0 = by * 128;

    // per-thread fill coordinates (fixed across k-steps)
    int frow[4], fc4[4];
#pragma unroll
    for (int s = 0; s < 4; s++) {
        int f = tid + s*256;
        frow[s] = f >> 3; fc4[s] = f & 7;
    }

    float c[2][8][4];
#pragma unroll
    for (int mi = 0; mi < 2; mi++)
#pragma unroll
        for (int ni = 0; ni < 8; ni++)
#pragma unroll
            for (int r = 0; r < 4; r++) c[mi][ni][r] = 0.0f;

    // prologue: load k0 = 0 tile into registers
    float4 sva[4], svb[4];
#pragma unroll
    for (int s = 0; s < 4; s++) {
        sva[s] = *(const float4*)&X[(size_t)(m0+frow[s])*256 + fc4[s]*4];
        svb[s] = *(const float4*)&W[(size_t)(o0+frow[s])*256 + fc4[s]*4];
    }

    for (int k0 = 0; k0 < 256; k0 += 32) {
        // store staged tile to smem (with tf32 cvt)
#pragma unroll
        for (int s = 0; s < 4; s++) {
            int row = frow[s], c4 = fc4[s];
            AsH[(c4*4+0)*ASTR + row] = tf32cvt(sva[s].x);
            AsH[(c4*4+1)*ASTR + row] = tf32cvt(sva[s].y);
            AsH[(c4*4+2)*ASTR + row] = tf32cvt(sva[s].z);
            AsH[(c4*4+3)*ASTR + row] = tf32cvt(sva[s].w);
            BsH[(c4*4+0)*ASTR + row] = tf32cvt(svb[s].x);
            BsH[(c4*4+1)*ASTR + row] = tf32cvt(svb[s].y);
            BsH[(c4*4+2)*ASTR + row] = tf32cvt(svb[s].z);
            BsH[(c4*4+3)*ASTR + row] = tf32cvt(svb[s].w);
        }
        __syncthreads();
        // prefetch next tile while MMAs run
        if (k0 + 32 < 256) {
#pragma unroll
            for (int s = 0; s < 4; s++) {
                sva[s] = *(const float4*)&X[(size_t)(m0+frow[s])*256 + (k0+32) + fc4[s]*4];
                svb[s] = *(const float4*)&W[(size_t)(o0+frow[s])*256 + (k0+32) + fc4[s]*4];
            }
        }
#pragma unroll
        for (int kh = 0; kh < 4; kh++) {
            int kb = kh*8;
            uint32_t aH[2][4];
#pragma unroll
            for (int mi = 0; mi < 2; mi++) {
                int rb = wm + mi*16 + g;
                aH[mi][0] = AsH[(kb+tk  )*ASTR + rb];
                aH[mi][1] = AsH[(kb+tk  )*ASTR + rb + 8];
                aH[mi][2] = AsH[(kb+tk+4)*ASTR + rb];
                aH[mi][3] = AsH[(kb+tk+4)*ASTR + rb + 8];
            }
            uint32_t bH[8][2];
#pragma unroll
            for (int ni = 0; ni < 8; ni++) {
                int nb = wn + ni*8 + g;
                bH[ni][0] = BsH[(kb+tk  )*ASTR + nb];
                bH[ni][1] = BsH[(kb+tk+4)*ASTR + nb];
            }
#pragma unroll
            for (int mi = 0; mi < 2; mi++)
#pragma unroll
                for (int ni = 0; ni < 8; ni++) {
                    float* cc = c[mi][ni];
                    mma_tf32(cc[0],cc[1],cc[2],cc[3],
                             aH[mi][0],aH[mi][1],aH[mi][2],aH[mi][3],
                             bH[ni][0],bH[ni][1]);
                }
        }
        __syncthreads();
    }

#pragma unroll
    for (int mi = 0; mi < 2; mi++)
#pragma unroll
        for (int ni = 0; ni < 8; ni++) {
            int o = o0 + wn + ni*8 + 2*tk;
            int h = o >> 5, dd = o & 31;
            int m = m0 + wm + mi*16 + g;
            int nb = m / L, gg = m % L;
            float* dst = &OUT[(((size_t)(nb*HN + h))*L + gg)*HDM + dd];
            *(float2*)dst = make_float2(c[mi][ni][0], c[mi][ni][1]);
            int m2 = m + 8;
            int nb2 = m2 / L, gg2 = m2 % L;
            float* dst2 = &OUT[(((size_t)(nb2*HN + h))*L + gg2)*HDM + dd];
            *(float2*)dst2 = make_float2(c[mi][ni][2], c[mi][ni][3]);
        }
}

// ---------------- mega kernel: logits (TF32 MMA) + 4x Sinkhorn, E in smem ---------
// blocks [0,128): one slice each, 512 threads; blocks [128,144): vembed.
__global__ __launch_bounds__(512) void k_mega(const float* __restrict__ Wvp,
                                              const float* __restrict__ Wvd,
                                              float* __restrict__ qout, int do_q) {
    extern __shared__ char smem[];
    int tid = threadIdx.x;
    int lane = tid & 31, w = tid >> 5;

    if (blockIdx.x >= NHS) {
        if (!do_q) return;
        float* sp   = (float*)smem;
        float* sd   = sp + DM;
        float* cnts = sd + DM;
        int n = blockIdx.x - NHS;
        if (tid < DM) {
            float accp = 0.0f, accd = 0.0f;
#pragma unroll
            for (int s = 0; s < SEG; s++) {
                accp += g_part[((0*NB + n)*SEG + s)*DM + tid];
                accd += g_part[((1*NB + n)*SEG + s)*DM + tid];
            }
            sp[tid] = accp; sd[tid] = accd;
        }
        if (tid < 2) {
            float c = 0.0f;
#pragma unroll
            for (int s = 0; s < SEG; s++) c += g_cpart[(tid*NB + n)*SEG + s];
            cnts[tid] = c;
        }
        __syncthreads();
        float cp = cnts[0], cd = cnts[1];
        for (int o = w; o < DM; o += 16) {
            float acc = 0.0f;
#pragma unroll
            for (int t = 0; t < 8; t++) {
                int k = lane + t*32;
                acc += sp[k]*Wvp[(size_t)o*DM + k] + sd[k]*Wvd[(size_t)o*DM + k];
            }
#pragma unroll
            for (int off = 16; off > 0; off >>= 1)
                acc += __shfl_xor_sync(0xFFFFFFFFu, acc, off);
            if (lane == 0) {
                qout[(size_t)n*512 + o]       = 0.5f * acc / cp;
                qout[(size_t)n*512 + 256 + o] = 0.5f * acc / cd;
            }
        }
        return;
    }

    // ---- per-slice logits + Sinkhorn ----
    int slice = blockIdx.x;
    int n = slice >> 3;
    const float* q = g_qd + (size_t)slice * GD * HDM;
    const float* k = g_kp + (size_t)slice * GP * HDM;

    __half*   Esm   = (__half*)(smem + SM_E);
    uint32_t* Qs    = (uint32_t*)(smem + SM_QK);
    uint32_t* Ks    = Qs + 32*ASTR;
    float*    strip = (float*)(smem + SM_QK);
    float*    mr    = (float*)(smem + SM_MR);
    float*    mc    = (float*)(smem + SM_MC);

    int g = lane >> 2, tk = lane & 3;
    int wm = (w & 3) * 32, wn = (w >> 2) * 32;

    // fill Q (128x32) once + fill coordinates
    int frow[2], fc4[2];
#pragma unroll
    for (int s = 0; s < 2; s++) {
        int f = tid + s*512;
        frow[s] = f >> 3; fc4[s] = f & 7;
        float4 v = *(const float4*)&q[(size_t)frow[s]*HDM + fc4[s]*4];
        Qs[(fc4[s]*4+0)*ASTR + frow[s]] = tf32cvt(v.x);
        Qs[(fc4[s]*4+1)*ASTR + frow[s]] = tf32cvt(v.y);
        Qs[(fc4[s]*4+2)*ASTR + frow[s]] = tf32cvt(v.z);
        Qs[(fc4[s]*4+3)*ASTR + frow[s]] = tf32cvt(v.w);
    }
    if (tid < 128) mr[tid] = g_md[n*GD + tid];
    mc[tid] = g_mp[n*GP + tid];

    // prologue: load K tile jt=0 into regs
    float4 skv[2];
#pragma unroll
    for (int s = 0; s < 2; s++)
        skv[s] = *(const float4*)&k[(size_t)frow[s]*HDM + fc4[s]*4];

    for (int jt = 0; jt < 4; jt++) {
        int j0 = jt * 128;
        // store staged K tile
#pragma unroll
        for (int s = 0; s < 2; s++) {
            Ks[(fc4[s]*4+0)*ASTR + frow[s]] = tf32cvt(skv[s].x);
            Ks[(fc4[s]*4+1)*ASTR + frow[s]] = tf32cvt(skv[s].y);
            Ks[(fc4[s]*4+2)*ASTR + frow[s]] = tf32cvt(skv[s].z);
            Ks[(fc4[s]*4+3)*ASTR + frow[s]] = tf32cvt(skv[s].w);
        }
        __syncthreads();
        // prefetch next K tile
        if (jt < 3) {
#pragma unroll
            for (int s = 0; s < 2; s++)
                skv[s] = *(const float4*)&k[(size_t)(j0+128+frow[s])*HDM + fc4[s]*4];
        }

        float c[2][4][4];
#pragma unroll
        for (int mi = 0; mi < 2; mi++)
#pragma unroll
            for (int ni = 0; ni < 4; ni++)
#pragma unroll
                for (int r = 0; r < 4; r++) c[mi][ni][r] = 0.0f;

#pragma unroll
        for (int kh = 0; kh < 4; kh++) {
            int kb = kh*8;
            uint32_t aH[2][4];
#pragma unroll
            for (int mi = 0; mi < 2; mi++) {
                int rb = wm + mi*16 + g;
                aH[mi][0] = Qs[(kb+tk  )*ASTR + rb];
                aH[mi][1] = Qs[(kb+tk  )*ASTR + rb + 8];
                aH[mi][2] = Qs[(kb+tk+4)*ASTR + rb];
                aH[mi][3] = Qs[(kb+tk+4)*ASTR + rb + 8];
            }
            uint32_t bH[4][2];
#pragma unroll
            for (int ni = 0; ni < 4; ni++) {
                int nb = wn + ni*8 + g;
                bH[ni][0] = Ks[(kb+tk  )*ASTR + nb];
                bH[ni][1] = Ks[(kb+tk+4)*ASTR + nb];
            }
#pragma unroll
            for (int mi = 0; mi < 2; mi++)
#pragma unroll
                for (int ni = 0; ni < 4; ni++) {
                    float* cc = c[mi][ni];
                    mma_tf32(cc[0],cc[1],cc[2],cc[3],
                             aH[mi][0],aH[mi][1],aH[mi][2],aH[mi][3],
                             bH[ni][0],bH[ni][1]);
                }
        }

        // epilogue: mask + ex2.f16x2, write into Esm
#pragma unroll
        for (int mi = 0; mi < 2; mi++) {
            int row1 = wm + mi*16 + g;
            int row2 = row1 + 8;
            float rm1 = mr[row1], rm2 = mr[row2];
#pragma unroll
            for (int ni = 0; ni < 4; ni++) {
                int o  = wn + ni*8 + 2*tk;
                int oc = j0 + o;
                float m0v = mc[oc], m1v = mc[oc+1];
                float* cc = c[mi][ni];
                __half2 xa = __floats2half2_rn(cc[0]*EXPSC, cc[1]*EXPSC);
                uint32_t ea = ex2_f16x2(*(uint32_t*)&xa);
                __half2 ma = __floats2half2_rn(rm1*m0v, rm1*m1v);
                *(__half2*)&Esm[row1*ESTR + oc] = __hmul2(*(__half2*)&ea, ma);
                __half2 xb = __floats2half2_rn(cc[2]*EXPSC, cc[3]*EXPSC);
                uint32_t eb = ex2_f16x2(*(uint32_t*)&xb);
                __half2 mb = __floats2half2_rn(rm2*m0v, rm2*m1v);
                *(__half2*)&Esm[row2*ESTR + oc] = __hmul2(*(__half2*)&eb, mb);
            }
        }
        __syncthreads();
    }

    // ---- 4 Sinkhorn iterations out of smem ----
    float cv[16];
#pragma unroll
    for (int u = 0; u < 16; u++) cv[u] = 1.0f;

    for (int iter = 0; iter < 4; iter++) {
        float colacc[16];
#pragma unroll
        for (int u = 0; u < 16; u++) colacc[u] = 0.0f;

#pragma unroll
        for (int ridx = 0; ridx < 8; ridx++) {
            int i = w + ridx*16;
            const uint4* rp = (const uint4*)(Esm + (size_t)i * ESTR);
            float ev[16];
            float s = 0.0f;
            uint4 raws[2];
#pragma unroll
            for (int ch = 0; ch < 2; ch++) {
                uint4 raw = rp[ch*32 + lane];
                raws[ch] = raw;
                float2 f0 = __half22float2(*(__half2*)&raw.x);
                float2 f1 = __half22float2(*(__half2*)&raw.y);
                float2 f2 = __half22float2(*(__half2*)&raw.z);
                float2 f3 = __half22float2(*(__half2*)&raw.w);
                ev[ch*8+0] = f0.x; ev[ch*8+1] = f0.y;
                ev[ch*8+2] = f1.x; ev[ch*8+3] = f1.y;
                ev[ch*8+4] = f2.x; ev[ch*8+5] = f2.y;
                ev[ch*8+6] = f3.x; ev[ch*8+7] = f3.y;
            }
#pragma unroll
            for (int u = 0; u < 16; u++) s += ev[u] * cv[u];
#pragma unroll
            for (int off = 16; off > 0; off >>= 1)
                s += __shfl_xor_sync(0xFFFFFFFFu, s, off);
            float r = (s > 0.0f) ? 1.0f/s : 0.0f;
            if (iter == 3) {
                if (lane == 0) g_r[slice*GD + i] = r;
                uint4* gp = (uint4*)(g_E + (size_t)slice*GD*GP + (size_t)i*GP);
                gp[lane]      = raws[0];
                gp[32 + lane] = raws[1];
            }
#pragma unroll
            for (int u = 0; u < 16; u++) colacc[u] += r * ev[u];
        }
#pragma unroll
        for (int u = 0; u < 16; u++) {
            int cc = (u >> 3)*256 + lane*8 + (u & 7);
            strip[w*544 + SIDX(cc)] = colacc[u];
        }
        __syncthreads();
        {
            int cc = tid;
            float s2 = 0.0f;
#pragma unroll
            for (int ww = 0; ww < 16; ww++) s2 += strip[ww*544 + SIDX(cc)];
            float rec = (s2 > 0.0f) ? 1.0f/s2 : 0.0f;
            if (iter == 3) g_c[slice*GP + cc] = rec;
            else           strip[SIDX(cc)] = rec;
        }
        __syncthreads();
        if (iter < 3) {
#pragma unroll
            for (int u = 0; u < 16; u++) {
                int cc = (u >> 3)*256 + lane*8 + (u & 7);
                cv[u] = strip[SIDX(cc)];
            }
            __syncthreads();
        }
    }
}

// ---------------- write a_dp = diag(r) E diag(c) in [n,i,j,h] layout --------------
__global__ __launch_bounds__(256) void k_adp(float* __restrict__ out) {
    __shared__ __half shE[8][512];
    __shared__ float  csh[8][512];
    __shared__ float  rsh[8];
    int b = blockIdx.x;
    int n = b >> 7, i = b & 127;
    int tid = threadIdx.x;

    if (tid < 8) rsh[tid] = g_r[(n*8 + tid)*GD + i];
#pragma unroll
    for (int t = 0; t < 2; t++) {
        int f = t*256 + tid;
        int h = f >> 6, qq = f & 63;
        ((uint4*)&shE[h][0])[qq] =
            ((const uint4*)(g_E + ((size_t)(n*8 + h)*GD + i)*GP))[qq];
    }
#pragma unroll
    for (int t = 0; t < 4; t++) {
        int f = t*256 + tid;
        int h = f >> 7, j4 = f & 127;
        ((float4*)&csh[h][0])[j4] =
            ((const float4*)(g_c + (size_t)(n*8 + h)*GP))[j4];
    }
    __syncthreads();

    float* dst = out + (size_t)b * GP * 8;
#pragma unroll
    for (int t = 0; t < 16; t++) {
        int o = t*256 + tid;
        int j = o >> 3, h = o & 7;
        float e = __half2float(shE[h][j]);
        dst[o] = rsh[h] * e * csh[h][j];
    }
}

// ---------------- launch -----------------------------------------------------------
extern "C" void kernel_launch(void* const* d_in, const int* in_sizes, int n_in,
                              void* d_out, int out_size) {
    const float* protein = (const float*)d_in[0];
    const float* drug    = (const float*)d_in[1];
    const void*  maskp   = d_in[2];
    const void*  maskd   = d_in[3];
    const float* Wk_p    = (const float*)d_in[5];
    const float* Wv_p    = (const float*)d_in[6];
    const float* Wq_d    = (const float*)d_in[7];
    const float* Wv_d    = (const float*)d_in[9];
    float* out = (float*)d_out;

    size_t adp_elems = (size_t)NB * GD * GP * HN;
    int  write_q   = (((size_t)out_size > adp_elems) || ((size_t)out_size < adp_elems)) ? 1 : 0;
    bool write_adp = ((size_t)out_size >= adp_elems);
    size_t adp_off = ((size_t)out_size >= adp_elems + NB*512) ? (size_t)NB*512 : 0;

    static int smem_set = 0;
    if (!smem_set) {
        cudaFuncSetAttribute(k_mega, cudaFuncAttributeMaxDynamicSharedMemorySize, SM_TOT);
        smem_set = 1;
    }

    k_probe<<<1, 256>>>((const unsigned int*)maskp);
    k_group2<<<NB*GP + NB*GD, 256>>>(protein, drug, maskp, maskd);
    k_fuse1<<<768, 256>>>(Wk_p, Wq_d);
    k_mega<<<NHS + NB, 512, SM_TOT>>>(Wv_p, Wv_d, out, write_q);
    if (write_adp) {
        k_adp<<<NB*GD, 256>>>(out + adp_off);
    }
}